// round 17
// baseline (speedup 1.0000x reference)
#include <cuda_runtime.h>
#include <cuda_fp16.h>
#include <math.h>

#define NTOT 8192
#define DD   128
#define EMBD 64
#define SL   7

// ---------------- scratch (device globals; no allocations) ----------------
__device__ float g_A [NTOT*DD];           // compact rows
__device__ float g_P [SL][NTOT*DD];       // L-pass K-slice partials
__device__ float g_PB[2][SL][NTOT*DD];    // B-pass partials
__device__ float g_PE[2][SL][NTOT*EMBD];  // E-pass partials
__device__ float g_Dk[2][NTOT*EMBD];      // compact rows
__device__ float g_Z [NTOT*EMBD];         // compact rows
__device__ int   g_cnt[NTOT];
__device__ int   g_nz[NTOT];              // nz row list (padded with 0)
__device__ int   g_rank[NTOT];            // original row -> compact index
__device__ int   g_nnz, g_npad, g_nm;

// transposed fp16 X operands ([C][NTOT], ORIGINAL indexing, zeros on cnt=0)
__device__ unsigned short g_xt [DD*NTOT];
__device__ unsigned short g_act[DD*NTOT];
__device__ unsigned short g_dt [2][EMBD*NTOT];

// fp16 K, rows compacted (nz), columns FULL (stride NTOT); written by B-pass
__device__ unsigned short g_kh[2][(size_t)NTOT*NTOT];

// ---------------- helpers ----------------
__device__ __forceinline__ unsigned smem_u32(const void* p) {
    unsigned a;
    asm("{ .reg .u64 t; cvta.to.shared.u64 t, %1; cvt.u32.u64 %0, t; }" : "=r"(a) : "l"(p));
    return a;
}
#define SWZ(o) ((o) ^ (((o) >> 3) & 0x70))

#define LDSM4(d0,d1,d2,d3,addr) \
    asm volatile("ldmatrix.sync.aligned.m8n8.x4.shared.b16 {%0,%1,%2,%3}, [%4];" \
        : "=r"(d0), "=r"(d1), "=r"(d2), "=r"(d3) : "r"(addr))

#define MMA16816(c, a, b) \
    asm volatile("mma.sync.aligned.m16n8k16.row.col.f32.f16.f16.f32 " \
        "{%0,%1,%2,%3},{%4,%5,%6,%7},{%8,%9},{%0,%1,%2,%3};" \
        : "+f"((c)[0]), "+f"((c)[1]), "+f"((c)[2]), "+f"((c)[3]) \
        : "r"((a)[0]), "r"((a)[1]), "r"((a)[2]), "r"((a)[3]), \
          "r"((b)[0]), "r"((b)[1]))

#define CP16(dst, src) \
    asm volatile("cp.async.cg.shared.global [%0], [%1], 16;" :: "r"(dst), "l"(src))
#define CP_COMMIT() asm volatile("cp.async.commit_group;" ::: "memory")
#define CP_WAIT0()  asm volatile("cp.async.wait_group 0;" ::: "memory")

// pack float pair to f16x2 (rn)
__device__ __forceinline__ unsigned pack2h(float f0, float f1) {
    unsigned r;
    asm("cvt.rn.f16x2.f32 %0, %1, %2;" : "=r"(r) : "f"(f1), "f"(f0));
    return r;
}

// ---------------- tiny kernels ----------------
__global__ void zero_cnt_kernel() {
    g_cnt[blockIdx.x*blockDim.x + threadIdx.x] = 0;
}
__global__ void count_kernel(const int* __restrict__ n_id) {
    atomicAdd(&g_cnt[n_id[blockIdx.x*blockDim.x + threadIdx.x]], 1);
}

// deterministic compaction scan
__global__ void scan_kernel() {
    __shared__ int ps[256];
    const int t = threadIdx.x;
    const int base = t * 32;
    int loc = 0;
    #pragma unroll
    for (int i = 0; i < 32; i++) loc += (g_cnt[base + i] > 0);
    ps[t] = loc;
    __syncthreads();
    for (int d = 1; d < 256; d <<= 1) {
        int v = (t >= d) ? ps[t - d] : 0;
        __syncthreads();
        ps[t] += v;
        __syncthreads();
    }
    int pos = ps[t] - loc;
    for (int i = 0; i < 32; i++) {
        int r = base + i;
        if (g_cnt[r] > 0) { g_nz[pos] = r; g_rank[r] = pos; pos++; }
    }
    if (t == 255) {
        int nnz = ps[255];
        g_nnz = nnz;
        int npad = (nnz + 63) & ~63;
        g_npad = npad;
        g_nm = npad >> 6;
    }
    __syncthreads();
    int nnz = g_nnz;
    for (int j = nnz + t; j < NTOT; j += 256) g_nz[j] = 0;
}

// ---------------- transpose + fp16 pack (original indexing, coalesced) ------
// SRC 0: x dense. SRC 2/3: g_Dk compact rows scattered to original idx (zeros
// where cnt==0).
template<int C, int SRC>
__global__ __launch_bounds__(256) void tsplit(const float* __restrict__ xext)
{
    const float* in;
    unsigned short* xo;
    if (SRC == 0)      { in = xext;    xo = g_xt; }
    else if (SRC == 2) { in = g_Dk[0]; xo = g_dt[0]; }
    else               { in = g_Dk[1]; xo = g_dt[1]; }

    __shared__ float tile[64][C + 4];
    const int t  = threadIdx.x;
    const int r0 = blockIdx.x * 64;
    constexpr int F4 = C / 4;
    #pragma unroll
    for (int i = 0; i < 64*F4/256; i++) {
        int u = t + i*256;
        int row = u / F4, c4 = u % F4;
        float4 v;
        if (SRC == 0) {
            v = *(const float4*)&in[(size_t)(r0+row)*C + c4*4];
        } else {
            int r = r0 + row;
            if (g_cnt[r] > 0)
                v = *(const float4*)&in[(size_t)g_rank[r]*C + c4*4];
            else
                v = make_float4(0.f, 0.f, 0.f, 0.f);
        }
        tile[row][c4*4+0] = v.x; tile[row][c4*4+1] = v.y;
        tile[row][c4*4+2] = v.z; tile[row][c4*4+3] = v.w;
    }
    __syncthreads();
    const int wid = t >> 5, lane = t & 31;
    const int r = 2*lane;
    for (int c = wid; c < C; c += 8) {
        *(unsigned*)&xo[(size_t)c*NTOT + r0 + r] = pack2h(tile[r][c], tile[r+1][c]);
    }
}

// ---- fused: A_c[rank] = x - tau*sum(P); act (original idx) = cnt*A ----
__global__ __launch_bounds__(256) void combine_tsplit(const float* __restrict__ x,
                                                      const float* __restrict__ taup)
{
    __shared__ float tile[64][DD + 4];
    const int t  = threadIdx.x;
    const int r0 = blockIdx.x * 64;
    const float tv = taup[0];
    #pragma unroll
    for (int i = 0; i < 8; i++) {
        int u = t + i*256;
        int row = u >> 5, c4 = u & 31;
        int r = r0 + row;
        int cn_i = g_cnt[r];
        if (cn_i > 0) {
            int j = g_rank[r];
            size_t oc = (size_t)j*DD + c4*4;
            float4 xv = *(const float4*)&x[(size_t)r*DD + c4*4];
            float4 ps = make_float4(0.f, 0.f, 0.f, 0.f);
            #pragma unroll
            for (int s = 0; s < SL; s++) {
                float4 p = *(const float4*)&g_P[s][oc];
                ps.x += p.x; ps.y += p.y; ps.z += p.z; ps.w += p.w;
            }
            float4 a;
            a.x = xv.x - tv*ps.x; a.y = xv.y - tv*ps.y;
            a.z = xv.z - tv*ps.z; a.w = xv.w - tv*ps.w;
            *(float4*)&g_A[oc] = a;
            float cn = (float)cn_i;
            tile[row][c4*4+0] = cn*a.x; tile[row][c4*4+1] = cn*a.y;
            tile[row][c4*4+2] = cn*a.z; tile[row][c4*4+3] = cn*a.w;
        } else {
            tile[row][c4*4+0] = 0.f; tile[row][c4*4+1] = 0.f;
            tile[row][c4*4+2] = 0.f; tile[row][c4*4+3] = 0.f;
        }
    }
    __syncthreads();
    const int wid = t >> 5, lane = t & 31;
    const int r = 2*lane;
    for (int c = wid; c < DD; c += 8) {
        *(unsigned*)&g_act[(size_t)c*NTOT + r0 + r] = pack2h(tile[r][c], tile[r+1][c]);
    }
}

// ---------------- HMMA GEMM: M-compact rows, FULL K, 1-limb fp16 ------------
// MODE 0: A=L rows nz (LDG+pack),            X=xt  -> g_P[s]
// MODE 1: A=K[y] rows nz (LDG+pack, writes g_kh),  X=act -> g_PB[y][s]
// MODE 2: A=g_kh[y] (cp.async),              X=dt  -> g_PE[y][s]
template<int NB, int MODE>
__global__ __launch_bounds__(256, 2) void gemm_hmma(const float* __restrict__ Mb)
{
    extern __shared__ char smem[];
    __shared__ int s_nzr[64];
    constexpr int NF  = NB / 32;
    constexpr int XSZ = NB * 128;          // X stage bytes
    constexpr int XU  = NB / 32;
    constexpr int STG = 8192 + XSZ;        // A + X per stage

    const int t = threadIdx.x, lane = t & 31, w = t >> 5;
    const int wm = w & 1, wn = w >> 1;
    const int NM = g_nm;
    const int NT = (MODE == 0) ? NM : 2*NM;
    const unsigned su = smem_u32(smem);

    const int arow = t >> 2;               // A-fill: 4 threads per row
    const int acq  = t & 3;                // 16 consecutive K per thread

    for (int q = blockIdx.x; q < NT*SL; q += gridDim.x) {
        const int tile = q % NT;
        const int s    = q / NT;
        const int m    = (MODE == 0) ? tile : (tile % NM);
        const int y    = (MODE == 0) ? 0    : (tile / NM);
        const int c0   = (s * 128) / SL;
        const int c1   = ((s + 1) * 128) / SL;

        const float* Mat = (MODE == 0) ? Mb : Mb + (size_t)y * NTOT * NTOT;
        const unsigned short* X;
        if (MODE == 0)      X = g_xt;
        else if (MODE == 1) X = g_act;
        else                X = g_dt[y];

        __syncthreads();   // smem stage + s_nzr reuse across items
        if (MODE != 2) {
            if (t < 64) s_nzr[t] = g_nz[m*64 + t];
            __syncthreads();
        }

        float acc[2][NF][4];
        #pragma unroll
        for (int mf = 0; mf < 2; mf++)
            #pragma unroll
            for (int nf = 0; nf < NF; nf++)
                #pragma unroll
                for (int j = 0; j < 4; j++) acc[mf][nf][j] = 0.f;

        float4 mv[4];

        auto LDG_MV = [&](int c) {
            if (MODE == 2) return;
            size_t rb = (size_t)s_nzr[arow]*NTOT + c*64 + acq*16;
            #pragma unroll
            for (int i = 0; i < 4; i++)
                mv[i] = *(const float4*)&Mat[rb + i*4];
        };
        auto FILL = [&](int c, int st) {
            const int k0 = c * 64;
            if (MODE == 2) {
                const unsigned ab = su + st*STG;
                #pragma unroll
                for (int i = 0; i < 2; i++) {
                    int u = t + (i << 8);
                    int row = u >> 3, j8 = u & 7;
                    unsigned off = SWZ((unsigned)(row*128 + j8*16));
                    size_t o = (size_t)(m*64 + row)*NTOT + k0 + j8*8;
                    CP16(ab + off, (const void*)&g_kh[y][o]);
                }
            } else {
                char* aB = smem + st*STG;
                uint4 q0, q1;
                q0.x = pack2h(mv[0].x, mv[0].y); q0.y = pack2h(mv[0].z, mv[0].w);
                q0.z = pack2h(mv[1].x, mv[1].y); q0.w = pack2h(mv[1].z, mv[1].w);
                q1.x = pack2h(mv[2].x, mv[2].y); q1.y = pack2h(mv[2].z, mv[2].w);
                q1.z = pack2h(mv[3].x, mv[3].y); q1.w = pack2h(mv[3].z, mv[3].w);
                unsigned base = (unsigned)(arow*128 + acq*32);
                *(uint4*)(aB + SWZ(base))      = q0;
                *(uint4*)(aB + SWZ(base + 16)) = q1;
                if (MODE == 1) {
                    size_t ko = (size_t)(m*64 + arow)*NTOT + k0 + acq*16;
                    *(uint4*)&g_kh[y][ko]     = q0;
                    *(uint4*)&g_kh[y][ko + 8] = q1;
                }
            }
            const unsigned xb = su + st*STG + 8192;
            #pragma unroll
            for (int i = 0; i < XU; i++) {
                int u = t + (i << 8);
                unsigned off = SWZ((unsigned)((u >> 3)*128 + (u & 7)*16));
                size_t o = (size_t)(u >> 3)*NTOT + k0 + ((u & 7) << 3);
                CP16(xb + off, (const void*)&X[o]);
            }
            CP_COMMIT();
        };

        LDG_MV(c0);
        FILL(c0, 0);
        if (c0 + 1 < c1) LDG_MV(c0 + 1);
        CP_WAIT0();
        __syncthreads();

        int st = 0;
        for (int c = c0; c < c1; c++) {
            const unsigned ab = su + st*STG;
            const unsigned xb = ab + 8192;

            auto KSTEP = [&](int kk) {
                const int kc2 = kk * 32;
                unsigned ah[2][4];
                #pragma unroll
                for (int mf = 0; mf < 2; mf++) {
                    int row = wm*32 + mf*16 + (lane & 15);
                    int kb  = kc2 + ((lane >> 4) << 4);
                    unsigned off = SWZ((unsigned)(row*128 + kb));
                    LDSM4(ah[mf][0], ah[mf][1], ah[mf][2], ah[mf][3], ab + off);
                }
                unsigned bx[NF][2];
                #pragma unroll
                for (int g = 0; g < NF/2; g++) {
                    int n  = wn*(NB/4) + g*16 + ((lane >> 4) << 3) + (lane & 7);
                    int kb = kc2 + (((lane >> 3) & 1) << 4);
                    unsigned off = SWZ((unsigned)(n*128 + kb));
                    LDSM4(bx[2*g][0], bx[2*g][1], bx[2*g+1][0], bx[2*g+1][1], xb + off);
                }
                #pragma unroll
                for (int nf = 0; nf < NF; nf++)
                    #pragma unroll
                    for (int mf = 0; mf < 2; mf++) MMA16816(acc[mf][nf], ah[mf], bx[nf]);
            };

            KSTEP(0);
            KSTEP(1);
            if (c + 1 < c1) {
                FILL(c + 1, st ^ 1);
                if (c + 2 < c1) LDG_MV(c + 2);
            }
            KSTEP(2);
            KSTEP(3);
            if (c + 1 < c1) {
                CP_WAIT0();
                __syncthreads();
            }
            st ^= 1;
        }

        // epilogue: write this slice's partial (compact rows)
        const int gid = lane >> 2, tig = lane & 3;
        float* O;
        int stride;
        if (MODE == 0)      { O = g_P[s];     stride = DD; }
        else if (MODE == 1) { O = g_PB[y][s]; stride = DD; }
        else                { O = g_PE[y][s]; stride = EMBD; }
        #pragma unroll
        for (int mf = 0; mf < 2; mf++) {
            int r = m*64 + wm*32 + mf*16 + gid;
            #pragma unroll
            for (int nf = 0; nf < NF; nf++) {
                int cc = wn*(NB/4) + nf*8 + 2*tig;
                *(float2*)&O[(size_t)r*stride + cc]     = make_float2(acc[mf][nf][0], acc[mf][nf][1]);
                *(float2*)&O[(size_t)(r+8)*stride + cc] = make_float2(acc[mf][nf][2], acc[mf][nf][3]);
            }
        }
    }
}

// ---------------- small fused projections (compact rows) ----------------
__global__ __launch_bounds__(256) void zd_kernel(const float* __restrict__ W)
{
    const int t  = threadIdx.x;
    const int r0 = blockIdx.x * 32;
    if (r0 >= g_npad) return;

    __shared__ float As [32][128];
    __shared__ float B0s[32][128];
    __shared__ float B1s[32][128];

    const int e  = t & 63;
    const int ry = t >> 6;

    #pragma unroll
    for (int i = 0; i < 4; i++) {
        int f = t + i*256;
        int row = f >> 5, c4 = f & 31;
        size_t o = (size_t)(r0+row)*DD + 4*c4;
        *(float4*)&As[row][4*c4] = *(const float4*)&g_A[o];
        float4 b0 = make_float4(0,0,0,0), b1 = make_float4(0,0,0,0);
        #pragma unroll
        for (int s = 0; s < SL; s++) {
            float4 p0 = *(const float4*)&g_PB[0][s][o];
            float4 p1 = *(const float4*)&g_PB[1][s][o];
            b0.x += p0.x; b0.y += p0.y; b0.z += p0.z; b0.w += p0.w;
            b1.x += p1.x; b1.y += p1.y; b1.z += p1.z; b1.w += p1.w;
        }
        *(float4*)&B0s[row][4*c4] = b0;
        *(float4*)&B1s[row][4*c4] = b1;
    }
    __syncthreads();

    float accZ[8], accD0[8], accD1[8];
    #pragma unroll
    for (int s = 0; s < 8; s++) { accZ[s] = 0.f; accD0[s] = 0.f; accD1[s] = 0.f; }

    for (int f = 0; f < 128; f++) {
        float wz0 = W[( 0  + f)*64 + e];
        float wz1 = W[(128 + f)*64 + e];
        float wz2 = W[(256 + f)*64 + e];
        float w00 = W[(384 + f)*64 + e];
        float w01 = W[(512 + f)*64 + e];
        float w10 = W[(640 + f)*64 + e];
        float w11 = W[(768 + f)*64 + e];
        #pragma unroll
        for (int s = 0; s < 8; s++) {
            int r = ry + 4*s;
            float a  = As [r][f];
            float b0 = B0s[r][f];
            float b1 = B1s[r][f];
            accZ [s] += a*wz0 + b0*wz1 + b1*wz2;
            accD0[s] += b0*w00 + b1*w01;
            accD1[s] += b0*w10 + b1*w11;
        }
    }
    #pragma unroll
    for (int s = 0; s < 8; s++) {
        int j = r0 + ry + 4*s;
        float cn = (float)g_cnt[g_nz[j]];
        g_Z    [(size_t)j*EMBD + e] = accZ[s];
        g_Dk[0][(size_t)j*EMBD + e] = cn * accD0[s];
        g_Dk[1][(size_t)j*EMBD + e] = cn * accD1[s];
    }
}

__global__ void final_kernel(const int* __restrict__ n_id,
                             const float* __restrict__ b,
                             float* __restrict__ out)
{
    int idx = blockIdx.x*blockDim.x + threadIdx.x;
    int j = idx >> 6, e = idx & 63;
    int cr = g_rank[n_id[j]];
    size_t zr = (size_t)cr*EMBD + e;
    float ev = 0.f;
    #pragma unroll
    for (int s = 0; s < SL; s++) ev += g_PE[0][s][zr] + g_PE[1][s][zr];
    out[idx] = tanhf(g_Z[zr] + ev + b[e]);
}

// ---------------- launch ----------------
extern "C" void kernel_launch(void* const* d_in, const int* in_sizes, int n_in,
                              void* d_out, int out_size)
{
    const float* x    = (const float*)d_in[0];
    const float* K    = (const float*)d_in[1];
    const float* L    = (const float*)d_in[2];
    const float* tau  = (const float*)d_in[3];
    const float* W    = (const float*)d_in[4];
    const float* b    = (const float*)d_in[5];
    const int*   n_id = (const int*)  d_in[6];
    float* out = (float*)d_out;

    const int SM128 = 2*(8192 + 128*128);   // 49152
    const int SM64  = 2*(8192 + 64*128);    // 32768
    cudaFuncSetAttribute(gemm_hmma<128,0>, cudaFuncAttributeMaxDynamicSharedMemorySize, SM128);
    cudaFuncSetAttribute(gemm_hmma<128,1>, cudaFuncAttributeMaxDynamicSharedMemorySize, SM128);
    cudaFuncSetAttribute(gemm_hmma<64,2>,  cudaFuncAttributeMaxDynamicSharedMemorySize, SM64);

    const int GRID = 304;   // 2 CTAs/SM x 152 SMs

    zero_cnt_kernel<<<NTOT/256, 256>>>();
    count_kernel   <<<NTOT/256, 256>>>(n_id);
    scan_kernel    <<<1, 256>>>();

    // x^T fp16 (full); L@x partials on nz rows (7 K-slices); fused combine
    tsplit<128,0><<<NTOT/64, 256>>>(x);
    gemm_hmma<128,0><<<GRID, 256, SM128>>>(L);
    combine_tsplit<<<NTOT/64, 256>>>(x, tau);

    // B_k = K[k] @ Ac (rows compact, FULL K; streams fp16 K rows to g_kh)
    gemm_hmma<128,1><<<GRID, 256, SM128>>>(K);

    // Z and D_k (sums B partials inline)
    zd_kernel<<<NTOT/32, 256>>>(W);

    // Dk^T fp16 (original idx, zeros on cnt=0); E_k = K[k] @ D_k (A cp.async)
    tsplit<64,2><<<NTOT/64, 256>>>(nullptr);
    tsplit<64,3><<<NTOT/64, 256>>>(nullptr);
    gemm_hmma<64,2><<<GRID, 256, SM64>>>(K);

    final_kernel<<<(NTOT*EMBD)/256, 256>>>(n_id, b, out);
}